// round 1
// baseline (speedup 1.0000x reference)
#include <cuda_runtime.h>

// Problem constants
#define B_  16
#define N_  64
#define S_  4
#define F0_ 8
#define C_  32
#define ROWS_ (B_*N_)     // 1024

// Scratch (device globals — no allocation allowed)
__device__ float g_U1[ROWS_*5*C_];     // U[row][s][x], s=4 is bias-kernel slot
__device__ float g_root1[ROWS_*C_];
__device__ float g_h1[ROWS_*C_];
__device__ float g_U2[ROWS_*5*C_];
__device__ float g_root2[ROWS_*C_];
__device__ float g_h2[ROWS_*C_];

// ---------------------------------------------------------------------------
// prep: U[row,s,x] = sum_y wk[s, x*FIN+y] * h[row,y]   (s=0..3)
//       U[row,4,x] = sum_y bk[x*FIN+y]   * h[row,y]
//       root[row,x] = bias[x] + sum_y wr[y,x] * h[row,y]
// One warp per row (row = b*N + i), lane = x channel.
// Weights staged transposed into smem so per-lane reads are conflict-free.
// ---------------------------------------------------------------------------
template<int FIN, int LAYER>
__global__ void prep_kernel(const float* __restrict__ hin,   // layer1: x (stride 9)
                            const float* __restrict__ wk,    // (S, C*FIN)
                            const float* __restrict__ bk,    // (C*FIN)
                            const float* __restrict__ wr,    // (FIN, C)
                            const float* __restrict__ bias)  // (C)
{
    __shared__ float wT[FIN][5][C_];   // wT[y][s][x]
    __shared__ float wrs[FIN][C_];     // wrs[y][x]
    __shared__ float bs[C_];

    const int tid = threadIdx.x;

    // Stage kernel weights transposed: wk[s*(C*FIN) + x*FIN + y] -> wT[y][s][x]
    for (int g = tid; g < S_*C_*FIN; g += blockDim.x) {
        int s  = g / (C_*FIN);
        int r  = g - s*(C_*FIN);
        int xx = r / FIN;
        int yy = r - xx*FIN;
        wT[yy][s][xx] = wk[g];
    }
    // Bias-kernel slot
    for (int g = tid; g < C_*FIN; g += blockDim.x) {
        int xx = g / FIN;
        int yy = g - xx*FIN;
        wT[yy][4][xx] = bk[g];
    }
    // Root weights: wr[y*C + x] layout already matches wrs[y][x]
    for (int g = tid; g < FIN*C_; g += blockDim.x)
        (&wrs[0][0])[g] = wr[g];
    if (tid < C_) bs[tid] = bias[tid];
    __syncthreads();

    const int row  = blockIdx.x * (blockDim.x >> 5) + (tid >> 5);
    const int lane = tid & 31;
    if (row >= ROWS_) return;

    // Input features for this row
    const float* h;
    int hstride;
    if (LAYER == 1) { h = hin;  hstride = F0_ + 1; }   // x, last column is mask
    else            { h = g_h1; hstride = C_;      }

    float hv_own = (lane < FIN) ? h[row*hstride + lane] : 0.f;

    float a0 = 0.f, a1 = 0.f, a2 = 0.f, a3 = 0.f, a4 = 0.f;
    float rt = bs[lane];
    #pragma unroll
    for (int y = 0; y < FIN; y++) {
        float hv = __shfl_sync(0xffffffffu, hv_own, y);
        a0 += wT[y][0][lane] * hv;
        a1 += wT[y][1][lane] * hv;
        a2 += wT[y][2][lane] * hv;
        a3 += wT[y][3][lane] * hv;
        a4 += wT[y][4][lane] * hv;
        rt += wrs[y][lane]   * hv;
    }

    float* U    = (LAYER == 1) ? g_U1    : g_U2;
    float* root = (LAYER == 1) ? g_root1 : g_root2;
    float* Ur = U + (size_t)row * 5 * C_;
    Ur[        lane] = a0;
    Ur[  C_ +  lane] = a1;
    Ur[2*C_ +  lane] = a2;
    Ur[3*C_ +  lane] = a3;
    Ur[4*C_ +  lane] = a4;
    root[row*C_ + lane] = rt;
}

// ---------------------------------------------------------------------------
// msg: h_out[b,t,x] = relu( (Σ_i Σ_s coeff_s(b,t,i)·U[b,i,s,x] + root[b,t,x]) * mask[b,t] )
// coeff_s = a*e_s for s<4, coeff_4 = a. Warp per (b,t), lane = x.
// Sparse skip on a[b,t,i]==0 (~92% of iterations).
// ---------------------------------------------------------------------------
template<int LAYER>
__global__ void msg_kernel(const float* __restrict__ a,
                           const float* __restrict__ e,
                           const float* __restrict__ xin)
{
    const int row  = blockIdx.x * (blockDim.x >> 5) + (threadIdx.x >> 5);
    const int lane = threadIdx.x & 31;
    if (row >= ROWS_) return;
    const int b = row >> 6;   // N_ == 64

    const float mask = xin[row*(F0_+1) + F0_];

    const float* U    = (LAYER == 1) ? g_U1    : g_U2;
    const float* root = (LAYER == 1) ? g_root1 : g_root2;
    float*       hout = (LAYER == 1) ? g_h1    : g_h2;

    float acc = 0.f;
    if (mask != 0.f) {
        const float*  arow = a + (size_t)row * N_;
        const float4* erow = (const float4*)(e + (size_t)row * N_ * S_);
        const float*  Ub   = U + (size_t)(b * N_) * 5 * C_;
        #pragma unroll 4
        for (int i = 0; i < N_; i++) {
            float av = arow[i];                 // warp-broadcast load
            if (av != 0.f) {
                float4 ev = erow[i];
                const float* Ui = Ub + i * 5 * C_;
                acc += (av*ev.x) * Ui[        lane];
                acc += (av*ev.y) * Ui[  C_ +  lane];
                acc += (av*ev.z) * Ui[2*C_ +  lane];
                acc += (av*ev.w) * Ui[3*C_ +  lane];
                acc +=  av       * Ui[4*C_ +  lane];
            }
        }
    }
    float val = (acc + root[row*C_ + lane]) * mask;
    hout[row*C_ + lane] = fmaxf(val, 0.f);
}

// ---------------------------------------------------------------------------
// pool + dense head: out[b] = Σ_{n,c} h2[b,n,c] * w_dense[c] + b_dense[0]
// (h2 already zero at masked rows). One block per batch element.
// ---------------------------------------------------------------------------
__global__ void pool_kernel(const float* __restrict__ wd,
                            const float* __restrict__ bd,
                            float* __restrict__ out)
{
    const int b   = blockIdx.x;
    const int tid = threadIdx.x;
    const float* hb = g_h2 + (size_t)b * N_ * C_;

    float part = 0.f;
    for (int idx = tid; idx < N_*C_; idx += blockDim.x)
        part += hb[idx] * wd[idx & (C_-1)];

    #pragma unroll
    for (int off = 16; off > 0; off >>= 1)
        part += __shfl_down_sync(0xffffffffu, part, off);

    __shared__ float red[8];
    if ((tid & 31) == 0) red[tid >> 5] = part;
    __syncthreads();
    if (tid < 8) {
        float v = red[tid];
        #pragma unroll
        for (int off = 4; off > 0; off >>= 1)
            v += __shfl_down_sync(0xffu, v, off);
        if (tid == 0) out[b] = v + bd[0];
    }
}

// ---------------------------------------------------------------------------
extern "C" void kernel_launch(void* const* d_in, const int* in_sizes, int n_in,
                              void* d_out, int out_size)
{
    const float* x       = (const float*)d_in[0];
    const float* a       = (const float*)d_in[1];
    const float* e       = (const float*)d_in[2];
    const float* w1_kern = (const float*)d_in[3];
    const float* b1_kern = (const float*)d_in[4];
    const float* w1_root = (const float*)d_in[5];
    const float* b1      = (const float*)d_in[6];
    const float* w2_kern = (const float*)d_in[7];
    const float* b2_kern = (const float*)d_in[8];
    const float* w2_root = (const float*)d_in[9];
    const float* b2      = (const float*)d_in[10];
    const float* w_dense = (const float*)d_in[11];
    const float* b_dense = (const float*)d_in[12];
    float* out = (float*)d_out;

    const dim3 blk(256);
    const int grid = ROWS_ / 8;   // 8 warps (rows) per block -> 128 blocks

    prep_kernel<F0_, 1><<<grid, blk>>>(x, w1_kern, b1_kern, w1_root, b1);
    msg_kernel<1><<<grid, blk>>>(a, e, x);
    prep_kernel<C_, 2><<<grid, blk>>>(x, w2_kern, b2_kern, w2_root, b2);
    msg_kernel<2><<<grid, blk>>>(a, e, x);
    pool_kernel<<<B_, 256>>>(w_dense, b_dense, out);
}

// round 2
// speedup vs baseline: 1.1745x; 1.1745x over previous
#include <cuda_runtime.h>

// Problem constants
#define B_  16
#define N_  64
#define S_  4
#define F0_ 8
#define C_  32
#define ROWS_ (B_*N_)     // 1024

// Scratch (device globals — no allocation allowed)
__device__ float g_U1[ROWS_*5*C_];     // U[row][s][x], s=4 is bias-kernel slot
__device__ float g_root1[ROWS_*C_];
__device__ float g_h1[ROWS_*C_];
__device__ float g_U2[ROWS_*5*C_];
__device__ float g_root2[ROWS_*C_];
__device__ float g_h2[ROWS_*C_];

// ---------------------------------------------------------------------------
// prep: U[row,s,x] = sum_y wk[s, x*FIN+y] * h[row,y]   (s=0..3)
//       U[row,4,x] = sum_y bk[x*FIN+y]   * h[row,y]
//       root[row,x] = bias[x] + sum_y wr[y,x] * h[row,y]
// One warp per ROWS_PER_WARP rows, lane = x channel.
// ---------------------------------------------------------------------------
template<int FIN, int LAYER, int RPW>
__global__ void prep_kernel(const float* __restrict__ hin,   // layer1: x (stride 9)
                            const float* __restrict__ wk,    // (S, C*FIN)
                            const float* __restrict__ bk,    // (C*FIN)
                            const float* __restrict__ wr,    // (FIN, C)
                            const float* __restrict__ bias)  // (C)
{
    __shared__ float wT[FIN][5][C_];   // wT[y][s][x]
    __shared__ float wrs[FIN][C_];     // wrs[y][x]
    __shared__ float bs[C_];

    const int tid = threadIdx.x;

    // Stage kernel weights transposed: wk[s*(C*FIN) + x*FIN + y] -> wT[y][s][x]
    for (int g = tid; g < S_*C_*FIN; g += blockDim.x) {
        int s  = g / (C_*FIN);
        int r  = g - s*(C_*FIN);
        int xx = r / FIN;
        int yy = r - xx*FIN;
        wT[yy][s][xx] = wk[g];
    }
    for (int g = tid; g < C_*FIN; g += blockDim.x) {
        int xx = g / FIN;
        int yy = g - xx*FIN;
        wT[yy][4][xx] = bk[g];
    }
    for (int g = tid; g < FIN*C_; g += blockDim.x)
        (&wrs[0][0])[g] = wr[g];
    if (tid < C_) bs[tid] = bias[tid];
    __syncthreads();

    const int warp = tid >> 5;
    const int lane = tid & 31;
    const int row0 = (blockIdx.x * (blockDim.x >> 5) + warp) * RPW;

    float* U    = (LAYER == 1) ? g_U1    : g_U2;
    float* root = (LAYER == 1) ? g_root1 : g_root2;

    #pragma unroll
    for (int r = 0; r < RPW; r++) {
        const int row = row0 + r;
        if (row >= ROWS_) break;

        const float* h;
        int hstride;
        if (LAYER == 1) { h = hin;  hstride = F0_ + 1; }
        else            { h = g_h1; hstride = C_;      }

        float hv_own = (lane < FIN) ? h[row*hstride + lane] : 0.f;

        float a0 = 0.f, a1 = 0.f, a2 = 0.f, a3 = 0.f, a4 = 0.f;
        float rt = bs[lane];
        #pragma unroll
        for (int y = 0; y < FIN; y++) {
            float hv = __shfl_sync(0xffffffffu, hv_own, y);
            a0 += wT[y][0][lane] * hv;
            a1 += wT[y][1][lane] * hv;
            a2 += wT[y][2][lane] * hv;
            a3 += wT[y][3][lane] * hv;
            a4 += wT[y][4][lane] * hv;
            rt += wrs[y][lane]   * hv;
        }

        float* Ur = U + (size_t)row * 5 * C_;
        Ur[        lane] = a0;
        Ur[  C_ +  lane] = a1;
        Ur[2*C_ +  lane] = a2;
        Ur[3*C_ +  lane] = a3;
        Ur[4*C_ +  lane] = a4;
        root[row*C_ + lane] = rt;
    }
}

// ---------------------------------------------------------------------------
// msg v2: 4 warps per row, each covering 16 neighbors i via ballot compaction.
// h_out[b,t,x] = relu( (Σ_i Σ_s coeff·U[b,i,s,x] + root) * mask )
// ---------------------------------------------------------------------------
template<int LAYER>
__global__ void msg_kernel(const float* __restrict__ a,
                           const float* __restrict__ e,
                           const float* __restrict__ xin)
{
    // 8 warps per block -> 2 rows per block, 4 warps per row
    const int warp     = threadIdx.x >> 5;
    const int lane     = threadIdx.x & 31;
    const int rowLocal = warp >> 2;      // 0..1
    const int wseg     = warp & 3;       // 0..3: which 16-slice of i
    const int row      = blockIdx.x * 2 + rowLocal;
    const int b        = row >> 6;       // N_ == 64

    __shared__ float red[2][4][C_];

    const float mask = xin[row*(F0_+1) + F0_];

    const float* U    = (LAYER == 1) ? g_U1    : g_U2;
    const float* root = (LAYER == 1) ? g_root1 : g_root2;
    float*       hout = (LAYER == 1) ? g_h1    : g_h2;

    float acc = 0.f;
    if (mask != 0.f) {
        const int i0 = wseg * 16;
        // Load this warp's 16 adjacency values once (coalesced 64B)
        float av_own = (lane < 16) ? a[(size_t)row * N_ + i0 + lane] : 0.f;
        unsigned nz = __ballot_sync(0xffffffffu, av_own != 0.f) & 0xFFFFu;

        const float4* erow = (const float4*)(e + (size_t)row * N_ * S_);
        const float*  Ub   = U + (size_t)(b * N_) * 5 * C_;

        while (nz) {
            const int j = __ffs(nz) - 1;
            nz &= nz - 1;
            const float av = __shfl_sync(0xffffffffu, av_own, j);
            const int i = i0 + j;
            const float4 ev = erow[i];               // warp-broadcast
            const float* Ui = Ub + i * 5 * C_;
            float u0 = Ui[        lane];
            float u1 = Ui[  C_ +  lane];
            float u2 = Ui[2*C_ +  lane];
            float u3 = Ui[3*C_ +  lane];
            float u4 = Ui[4*C_ +  lane];
            acc += (av*ev.x) * u0;
            acc += (av*ev.y) * u1;
            acc += (av*ev.z) * u2;
            acc += (av*ev.w) * u3;
            acc +=  av       * u4;
        }
    }

    red[rowLocal][wseg][lane] = acc;
    __syncthreads();

    if (wseg == 0) {
        float total = red[rowLocal][0][lane] + red[rowLocal][1][lane]
                    + red[rowLocal][2][lane] + red[rowLocal][3][lane];
        float val = (total + root[row*C_ + lane]) * mask;
        hout[row*C_ + lane] = fmaxf(val, 0.f);
    }
}

// ---------------------------------------------------------------------------
// pool + dense head: out[b] = Σ_{n,c} h2[b,n,c] * w_dense[c] + b_dense[0]
// ---------------------------------------------------------------------------
__global__ void pool_kernel(const float* __restrict__ wd,
                            const float* __restrict__ bd,
                            float* __restrict__ out)
{
    const int b   = blockIdx.x;
    const int tid = threadIdx.x;
    const float* hb = g_h2 + (size_t)b * N_ * C_;

    float part = 0.f;
    for (int idx = tid; idx < N_*C_; idx += blockDim.x)
        part += hb[idx] * wd[idx & (C_-1)];

    #pragma unroll
    for (int off = 16; off > 0; off >>= 1)
        part += __shfl_down_sync(0xffffffffu, part, off);

    __shared__ float red[8];
    if ((tid & 31) == 0) red[tid >> 5] = part;
    __syncthreads();
    if (tid < 8) {
        float v = red[tid];
        #pragma unroll
        for (int off = 4; off > 0; off >>= 1)
            v += __shfl_down_sync(0xffu, v, off);
        if (tid == 0) out[b] = v + bd[0];
    }
}

// ---------------------------------------------------------------------------
extern "C" void kernel_launch(void* const* d_in, const int* in_sizes, int n_in,
                              void* d_out, int out_size)
{
    const float* x       = (const float*)d_in[0];
    const float* a       = (const float*)d_in[1];
    const float* e       = (const float*)d_in[2];
    const float* w1_kern = (const float*)d_in[3];
    const float* b1_kern = (const float*)d_in[4];
    const float* w1_root = (const float*)d_in[5];
    const float* b1      = (const float*)d_in[6];
    const float* w2_kern = (const float*)d_in[7];
    const float* b2_kern = (const float*)d_in[8];
    const float* w2_root = (const float*)d_in[9];
    const float* b2      = (const float*)d_in[10];
    const float* w_dense = (const float*)d_in[11];
    const float* b_dense = (const float*)d_in[12];
    float* out = (float*)d_out;

    const dim3 blk(256);

    // prep1: 8 warps/block, 1 row/warp -> 128 blocks (cheap smem staging, FIN=8)
    prep_kernel<F0_, 1, 1><<<ROWS_/8, blk>>>(x, w1_kern, b1_kern, w1_root, b1);
    // msg1: 2 rows per block -> 512 blocks
    msg_kernel<1><<<ROWS_/2, blk>>>(a, e, x);
    // prep2: FIN=32 -> heavy 25KB staging; 4 rows/warp -> 32 blocks
    prep_kernel<C_, 2, 4><<<ROWS_/(8*4), blk>>>(x, w2_kern, b2_kern, w2_root, b2);
    // msg2
    msg_kernel<2><<<ROWS_/2, blk>>>(a, e, x);
    pool_kernel<<<B_, 256>>>(w_dense, b_dense, out);
}